// round 1
// baseline (speedup 1.0000x reference)
#include <cuda_runtime.h>
#include <math.h>

// Problem constants (fixed shapes)
#define BB 4
#define HH 64
#define WW 64
#define FF 256
#define CC 19
#define SS 256
#define TWOS (2*SS)            // 512
#define NN (BB*HH*WW)          // 16384 pixels
#define MM (CC*TWOS)           // 9728 memory vectors
#define INV_TEMP 2.0f          // 1/0.5

// Scratch (static device globals; no allocation at runtime)
__device__ float g_featsNT[FF * NN];     // [f][n], normalized feats (16 MB)
__device__ float g_memN[MM * FF];        // [m][f], normalized memory (10 MB)
__device__ float g_total[NN];            // per-pixel sum of exp(cos/temp)
__device__ float g_owncos[NN * TWOS];    // per-pixel own-class-block cos (33.5 MB)
__device__ float g_pixterm[NN];          // per-pixel positive-term sum

// ---------------------------------------------------------------------------
// K1a: normalize feats. pred_rep is (B,F,H,W). Write transposed [f][n].
// Also zero g_total (rewritten every launch -> deterministic across replays).
// ---------------------------------------------------------------------------
__global__ void k_feats_norm(const float* __restrict__ pred) {
    int t = threadIdx.x;
    int w = t & 63;
    int h = blockIdx.y * 4 + (t >> 6);
    int b = blockIdx.x;
    int n = (b * HH + h) * WW + w;

    float sumsq = 0.0f;
    #pragma unroll 8
    for (int f = 0; f < FF; f++) {
        float v = pred[((b * FF + f) * HH + h) * WW + w];
        sumsq += v * v;
    }
    float inv = rsqrtf(sumsq);
    #pragma unroll 8
    for (int f = 0; f < FF; f++) {
        float v = pred[((b * FF + f) * HH + h) * WW + w];
        g_featsNT[f * NN + n] = v * inv;
    }
    g_total[n] = 0.0f;
}

// ---------------------------------------------------------------------------
// K1b: normalize memory rows. One block per row, 256 threads (one per f).
// ---------------------------------------------------------------------------
__global__ void k_mem_norm(const float* __restrict__ mem) {
    __shared__ float red[8];
    __shared__ float s_inv;
    int m = blockIdx.x;
    int t = threadIdx.x;
    float v = mem[m * FF + t];
    float p = v * v;
    // warp reduce
    #pragma unroll
    for (int o = 16; o > 0; o >>= 1) p += __shfl_down_sync(0xffffffffu, p, o);
    if ((t & 31) == 0) red[t >> 5] = p;
    __syncthreads();
    if (t == 0) {
        float s = 0.0f;
        #pragma unroll
        for (int i = 0; i < 8; i++) s += red[i];
        s_inv = rsqrtf(s);
    }
    __syncthreads();
    g_memN[m * FF + t] = v * s_inv;
}

// ---------------------------------------------------------------------------
// K2: fused GEMM + exp/row-sum + own-block cos scatter.
// Tile 128 pixels x 128 mems x K-chunk 16. 256 threads, 8x8 per thread.
// m-tiles of 128 never straddle 512-wide class blocks.
// ---------------------------------------------------------------------------
__global__ __launch_bounds__(256, 2) void k_gemm_exp(const int* __restrict__ labels) {
    __shared__ float As[16][128];       // [k][pixel]
    __shared__ float Bs[16][132];       // [k][mem], padded
    __shared__ float rowsum[128];

    int t  = threadIdx.x;
    int tx = t & 15;          // mem group
    int ty = t >> 4;          // pixel group
    int m0 = blockIdx.x * 128;
    int n0 = blockIdx.y * 128;

    float acc[8][8];
    #pragma unroll
    for (int i = 0; i < 8; i++)
        #pragma unroll
        for (int j = 0; j < 8; j++) acc[i][j] = 0.0f;

    for (int k0 = 0; k0 < FF; k0 += 16) {
        // Load A tile: g_featsNT[(k0+kk)*NN + n0 + c], 2048 floats
        #pragma unroll
        for (int i = 0; i < 2; i++) {
            int idx = i * 256 + t;            // 0..511 float4s
            int kk  = idx >> 5;
            int c4  = (idx & 31) << 2;
            float4 v = *(const float4*)&g_featsNT[(k0 + kk) * NN + n0 + c4];
            *(float4*)&As[kk][c4] = v;
        }
        // Load B tile (transpose to [k][m]): g_memN[(m0+m)*FF + k0 + kg]
        #pragma unroll
        for (int i = 0; i < 2; i++) {
            int idx = i * 256 + t;            // 0..511 float4s
            int m   = idx >> 2;
            int kg  = (idx & 3) << 2;
            float4 v = *(const float4*)&g_memN[(m0 + m) * FF + k0 + kg];
            Bs[kg + 0][m] = v.x;
            Bs[kg + 1][m] = v.y;
            Bs[kg + 2][m] = v.z;
            Bs[kg + 3][m] = v.w;
        }
        __syncthreads();
        #pragma unroll
        for (int kk = 0; kk < 16; kk++) {
            float a[8], b[8];
            *(float4*)&a[0] = *(const float4*)&As[kk][ty * 8 + 0];
            *(float4*)&a[4] = *(const float4*)&As[kk][ty * 8 + 4];
            *(float4*)&b[0] = *(const float4*)&Bs[kk][tx * 8 + 0];
            *(float4*)&b[4] = *(const float4*)&Bs[kk][tx * 8 + 4];
            #pragma unroll
            for (int i = 0; i < 8; i++)
                #pragma unroll
                for (int j = 0; j < 8; j++)
                    acc[i][j] += a[i] * b[j];
        }
        __syncthreads();
    }

    // Epilogue: exp + row sums + own-class cos scatter
    int tileClass = m0 >> 9;     // whole tile is inside one class block
    if (t < 128) rowsum[t] = 0.0f;
    __syncthreads();

    #pragma unroll
    for (int i = 0; i < 8; i++) {
        int r = ty * 8 + i;
        int n = n0 + r;
        bool own = (labels[n] == tileClass);
        float rs = 0.0f;
        #pragma unroll
        for (int j = 0; j < 8; j++) {
            float cosv = acc[i][j];
            rs += __expf(INV_TEMP * cosv);
            if (own) {
                int m = m0 + tx * 8 + j;
                g_owncos[n * TWOS + (m - (tileClass << 9))] = cosv;
            }
        }
        atomicAdd(&rowsum[r], rs);
    }
    __syncthreads();
    if (t < 128) atomicAdd(&g_total[n0 + t], rowsum[t]);
}

// ---------------------------------------------------------------------------
// K3: one warp per pixel. Recompute block sum from stored cos, get down,
// sum -log(pos/(pos+down+eps)+eps) over the wm-selected half.
// ---------------------------------------------------------------------------
__global__ void k_terms(const unsigned char* __restrict__ mask,
                        const int* __restrict__ wm) {
    int gw   = (blockIdx.x * blockDim.x + threadIdx.x) >> 5;
    int lane = threadIdx.x & 31;
    if (gw >= NN) return;
    int n = gw;

    float e[16];
    float bs = 0.0f;
    #pragma unroll
    for (int k = 0; k < 16; k++) {
        float c = g_owncos[n * TWOS + lane + 32 * k];
        float ev = __expf(INV_TEMP * c);
        e[k] = ev;
        bs += ev;
    }
    #pragma unroll
    for (int o = 16; o > 0; o >>= 1) bs += __shfl_xor_sync(0xffffffffu, bs, o);

    float down = g_total[n] - bs;
    int wv = wm[n];
    // wm==1 -> net 0 -> first half (k<8); wm==0 -> net 1 -> second half
    float ts = 0.0f;
    #pragma unroll
    for (int k = 0; k < 16; k++) {
        bool inHalf = (wv == 1) ? (k < 8) : (k >= 8);
        if (inHalf) {
            float pos = e[k];
            float r = pos / (pos + down + 1e-12f);
            ts += -logf(r + 1e-12f);
        }
    }
    #pragma unroll
    for (int o = 16; o > 0; o >>= 1) ts += __shfl_xor_sync(0xffffffffu, ts, o);

    if (lane == 0) g_pixterm[n] = mask[n] ? ts : 0.0f;
}

// ---------------------------------------------------------------------------
// K4: per-class reduction -> final scalar.
// ---------------------------------------------------------------------------
__global__ void k_final(const int* __restrict__ labels,
                        const unsigned char* __restrict__ mask,
                        float* __restrict__ out) {
    __shared__ float contrib[CC];
    __shared__ int   cnt[CC];
    int t = threadIdx.x;
    if (t < CC) { contrib[t] = 0.0f; cnt[t] = 0; }
    __syncthreads();
    for (int n = t; n < NN; n += blockDim.x) {
        if (mask[n]) {
            int c = labels[n];
            atomicAdd(&contrib[c], g_pixterm[n]);
            atomicAdd(&cnt[c], 1);
        }
    }
    __syncthreads();
    if (t == 0) {
        float loss = 0.0f, ccount = 0.0f;
        for (int i = 0; i < CC; i++) {
            if (cnt[i] > 0) {
                loss += contrib[i] / ((float)cnt[i] * (float)SS);
                ccount += 1.0f;
            }
        }
        out[0] = loss / fmaxf(ccount, 1.0f);
    }
}

// ---------------------------------------------------------------------------
extern "C" void kernel_launch(void* const* d_in, const int* in_sizes, int n_in,
                              void* d_out, int out_size) {
    const float*         mem    = (const float*)d_in[0];         // (19,512,256)
    const float*         pred   = (const float*)d_in[1];         // (4,256,64,64)
    const int*           labels = (const int*)d_in[2];           // (4,64,64)
    const unsigned char* mask   = (const unsigned char*)d_in[3]; // bool (1B)
    const int*           wm     = (const int*)d_in[4];           // (4,64,64)
    float*               out    = (float*)d_out;

    (void)in_sizes; (void)n_in; (void)out_size;

    k_feats_norm<<<dim3(BB, HH / 4), 256>>>(pred);
    k_mem_norm<<<MM, 256>>>(mem);
    k_gemm_exp<<<dim3(MM / 128, NN / 128), 256>>>(labels);
    k_terms<<<NN / 8, 256>>>(mask, wm);
    k_final<<<1, 256>>>(labels, mask, out);
}

// round 4
// speedup vs baseline: 4.4865x; 4.4865x over previous
#include <cuda_runtime.h>
#include <cuda_bf16.h>
#include <math.h>
#include <stdint.h>

// Problem constants (fixed shapes)
#define BB 4
#define HH 64
#define WW 64
#define FF 256
#define CC 19
#define SS 256
#define TWOS (2*SS)            // 512
#define NN (BB*HH*WW)          // 16384 pixels
#define MM (CC*TWOS)           // 9728 memory vectors

// Scratch (static device globals; no allocation at runtime)
__device__ __nv_bfloat16 g_A[NN * FF];   // normalized feats, [n][f] row-major (8 MB)
__device__ __nv_bfloat16 g_Bm[MM * FF];  // normalized memory, [m][f] row-major (5 MB)
__device__ float g_total[NN];            // per-pixel sum of exp(cos/temp)
__device__ float g_owncos[NN * TWOS];    // per-pixel own-class-block cos (33.5 MB)
__device__ float g_pixterm[NN];          // per-pixel positive-term sum

// ---------------------------------------------------------------------------
// exp(2*c) on the FMA pipe: 2^(c*2*log2e), range-reduce + deg-5 Taylor +
// exponent splice. c in [-1.01, 1.01] -> y in [-2.92, 2.92], n in [-3,3],
// p in [0.70, 1.42] (positive normal), rel err ~2.4e-6.
// ---------------------------------------------------------------------------
__device__ __forceinline__ float fexp2c(float c) {
    float y = c * 2.8853900817779268f;   // 2 * log2(e)
    float n = rintf(y);
    float t = (y - n) * 0.6931471805599453f;
    float p = 1.0f + t * (1.0f + t * (0.5f + t * (0.16666667f
                  + t * (0.041666668f + t * 0.008333334f))));
    return __int_as_float(__float_as_int(p) + (((int)n) << 23));
}

__device__ __forceinline__ void cp16(void* smem_dst, const void* gsrc) {
    uint32_t d = (uint32_t)__cvta_generic_to_shared(smem_dst);
    asm volatile("cp.async.cg.shared.global [%0], [%1], 16;\n" :: "r"(d), "l"(gsrc));
}

__device__ __forceinline__ void mma16816(float* d, const uint32_t* a, const uint32_t* b) {
    asm volatile(
        "mma.sync.aligned.m16n8k16.row.col.f32.bf16.bf16.f32 "
        "{%0,%1,%2,%3}, {%4,%5,%6,%7}, {%8,%9}, {%0,%1,%2,%3};\n"
        : "+f"(d[0]), "+f"(d[1]), "+f"(d[2]), "+f"(d[3])
        : "r"(a[0]), "r"(a[1]), "r"(a[2]), "r"(a[3]), "r"(b[0]), "r"(b[1]));
}

// ---------------------------------------------------------------------------
// K1a: normalize feats. pred_rep is (B,F,H,W). Write bf16 [n][f] row-major.
// One thread per pixel (coalesced across w). Also zero g_total.
// ---------------------------------------------------------------------------
__global__ void k_prep_feats(const float* __restrict__ pred) {
    int t = threadIdx.x;
    int w = t & 63;
    int h = blockIdx.y * 4 + (t >> 6);
    int b = blockIdx.x;
    int n = (b * HH + h) * WW + w;
    const float* base = pred + (size_t)b * FF * HH * WW + h * WW + w;

    float sumsq = 0.0f;
    #pragma unroll 8
    for (int f = 0; f < FF; f++) {
        float v = base[f * (HH * WW)];
        sumsq += v * v;
    }
    float inv = rsqrtf(sumsq);

    for (int f0 = 0; f0 < FF; f0 += 8) {
        __nv_bfloat16 h8[8];
        #pragma unroll
        for (int j = 0; j < 8; j++)
            h8[j] = __float2bfloat16(base[(f0 + j) * (HH * WW)] * inv);
        *(uint4*)&g_A[n * FF + f0] = *(const uint4*)h8;
    }
    g_total[n] = 0.0f;
}

// ---------------------------------------------------------------------------
// K1b: normalize memory rows -> bf16 [m][f]. One block (128 thr) per row.
// ---------------------------------------------------------------------------
__global__ void k_prep_mem(const float* __restrict__ mem) {
    __shared__ float red[4];
    int m = blockIdx.x;
    int t = threadIdx.x;
    float2 v = *(const float2*)&mem[m * FF + 2 * t];
    float p = v.x * v.x + v.y * v.y;
    #pragma unroll
    for (int o = 16; o > 0; o >>= 1) p += __shfl_down_sync(0xffffffffu, p, o);
    if ((t & 31) == 0) red[t >> 5] = p;
    __syncthreads();
    float inv = rsqrtf(red[0] + red[1] + red[2] + red[3]);
    __nv_bfloat162 o2;
    o2.x = __float2bfloat16(v.x * inv);
    o2.y = __float2bfloat16(v.y * inv);
    *(__nv_bfloat162*)&g_Bm[m * FF + 2 * t] = o2;
}

// ---------------------------------------------------------------------------
// K2: bf16 tensor-core GEMM (128 pix x 128 mem x K=256) + poly-exp row sums
// + own-class cos scatter. 8 warps, warp tile 32x64, mma.m16n8k16,
// cp.async double-buffered BK=32.
// ---------------------------------------------------------------------------
#define SMROW 40   // 32 bf16 data + 8 pad (conflict-free frag loads)

__global__ __launch_bounds__(256) void k_gemm(const int* __restrict__ labels) {
    __shared__ __align__(16) __nv_bfloat16 As[2][128 * SMROW];
    __shared__ __align__(16) __nv_bfloat16 Bs[2][128 * SMROW];
    __shared__ float s_rowsum[128];
    __shared__ int   s_lab[128];

    int tid = threadIdx.x;
    int m0 = blockIdx.x * 128;
    int n0 = blockIdx.y * 128;
    int wid = tid >> 5, lane = tid & 31;
    int wm = wid & 3;          // pixel-dir warp (4)
    int wn = wid >> 2;         // mem-dir warp (2)
    int g = lane >> 2, t4 = lane & 3;

    if (tid < 128) { s_rowsum[tid] = 0.0f; s_lab[tid] = labels[n0 + tid]; }

    float acc[2][8][4];
    #pragma unroll
    for (int mi = 0; mi < 2; mi++)
        #pragma unroll
        for (int ni = 0; ni < 8; ni++)
            #pragma unroll
            for (int q = 0; q < 4; q++) acc[mi][ni][q] = 0.0f;

#define ISSUE(IT, BUF) do {                                                   \
        int k0_ = (IT) * 32;                                                  \
        _Pragma("unroll")                                                     \
        for (int r2 = 0; r2 < 2; r2++) {                                      \
            int id = tid + r2 * 256;                                          \
            int row = id >> 2, c = id & 3;                                    \
            cp16(&As[BUF][row * SMROW + c * 8], &g_A[(n0 + row) * FF + k0_ + c * 8]);  \
            cp16(&Bs[BUF][row * SMROW + c * 8], &g_Bm[(m0 + row) * FF + k0_ + c * 8]); \
        } } while (0)

    ISSUE(0, 0);
    asm volatile("cp.async.commit_group;\n");

    for (int it = 0; it < 8; it++) {
        int buf = it & 1;
        if (it < 7) ISSUE(it + 1, buf ^ 1);
        asm volatile("cp.async.commit_group;\n");
        asm volatile("cp.async.wait_group 1;\n");
        __syncthreads();

        const uint32_t* A32 = (const uint32_t*)As[buf];
        const uint32_t* B32 = (const uint32_t*)Bs[buf];
        #pragma unroll
        for (int ks = 0; ks < 2; ks++) {
            uint32_t a[2][4], b[8][2];
            #pragma unroll
            for (int mi = 0; mi < 2; mi++) {
                int r0 = wm * 32 + mi * 16;
                a[mi][0] = A32[(r0 + g)     * (SMROW/2) + ks * 8     + t4];
                a[mi][1] = A32[(r0 + 8 + g) * (SMROW/2) + ks * 8     + t4];
                a[mi][2] = A32[(r0 + g)     * (SMROW/2) + ks * 8 + 4 + t4];
                a[mi][3] = A32[(r0 + 8 + g) * (SMROW/2) + ks * 8 + 4 + t4];
            }
            #pragma unroll
            for (int ni = 0; ni < 8; ni++) {
                int c0 = wn * 64 + ni * 8;
                b[ni][0] = B32[(c0 + g) * (SMROW/2) + ks * 8     + t4];
                b[ni][1] = B32[(c0 + g) * (SMROW/2) + ks * 8 + 4 + t4];
            }
            #pragma unroll
            for (int mi = 0; mi < 2; mi++)
                #pragma unroll
                for (int ni = 0; ni < 8; ni++)
                    mma16816(acc[mi][ni], a[mi], b[ni]);
        }
        __syncthreads();
    }
#undef ISSUE

    // Epilogue: poly exp + row sums + own-class cos scatter
    int cls = m0 >> 9;                       // tile never straddles class blocks
    int mrel = (m0 - (cls << 9)) + wn * 64;  // offset within 512-wide class block

    #pragma unroll
    for (int mi = 0; mi < 2; mi++) {
        int rbase = wm * 32 + mi * 16;
        int p0 = rbase + g;
        int p1 = rbase + 8 + g;
        bool own0 = (s_lab[p0] == cls);
        bool own1 = (s_lab[p1] == cls);
        float s0 = 0.0f, s1 = 0.0f;
        #pragma unroll
        for (int ni = 0; ni < 8; ni++) {
            float d0 = acc[mi][ni][0], d1 = acc[mi][ni][1];
            float d2 = acc[mi][ni][2], d3 = acc[mi][ni][3];
            s0 += fexp2c(d0) + fexp2c(d1);
            s1 += fexp2c(d2) + fexp2c(d3);
            int mo = mrel + ni * 8 + t4 * 2;
            if (own0) {
                g_owncos[(n0 + p0) * TWOS + mo]     = d0;
                g_owncos[(n0 + p0) * TWOS + mo + 1] = d1;
            }
            if (own1) {
                g_owncos[(n0 + p1) * TWOS + mo]     = d2;
                g_owncos[(n0 + p1) * TWOS + mo + 1] = d3;
            }
        }
        s0 += __shfl_xor_sync(0xffffffffu, s0, 1);
        s0 += __shfl_xor_sync(0xffffffffu, s0, 2);
        s1 += __shfl_xor_sync(0xffffffffu, s1, 1);
        s1 += __shfl_xor_sync(0xffffffffu, s1, 2);
        if (t4 == 0) {
            atomicAdd(&s_rowsum[p0], s0);
            atomicAdd(&s_rowsum[p1], s1);
        }
    }
    __syncthreads();
    if (tid < 128) atomicAdd(&g_total[n0 + tid], s_rowsum[tid]);
}

// ---------------------------------------------------------------------------
// K3: one warp per pixel. Recompute block sum (same poly as GEMM epilogue),
// get down, sum -log(pos/(pos+down+eps)+eps) over the wm-selected half.
// ---------------------------------------------------------------------------
__global__ void k_terms(const unsigned char* __restrict__ mask,
                        const int* __restrict__ wm) {
    int gw   = (blockIdx.x * blockDim.x + threadIdx.x) >> 5;
    int lane = threadIdx.x & 31;
    if (gw >= NN) return;
    int n = gw;

    float e[16];
    float bs = 0.0f;
    #pragma unroll
    for (int k = 0; k < 16; k++) {
        float c = g_owncos[n * TWOS + lane + 32 * k];
        float ev = fexp2c(c);
        e[k] = ev;
        bs += ev;
    }
    #pragma unroll
    for (int o = 16; o > 0; o >>= 1) bs += __shfl_xor_sync(0xffffffffu, bs, o);

    float down = g_total[n] - bs;
    int wv = wm[n];
    // wm==1 -> net 0 -> first half (k<8); wm==0 -> net 1 -> second half
    float ts = 0.0f;
    #pragma unroll
    for (int k = 0; k < 16; k++) {
        bool inHalf = (wv == 1) ? (k < 8) : (k >= 8);
        if (inHalf) {
            float pos = e[k];
            float r = pos / (pos + down + 1e-12f);
            ts += -logf(r + 1e-12f);
        }
    }
    #pragma unroll
    for (int o = 16; o > 0; o >>= 1) ts += __shfl_xor_sync(0xffffffffu, ts, o);

    if (lane == 0) g_pixterm[n] = mask[n] ? ts : 0.0f;
}

// ---------------------------------------------------------------------------
// K4: per-class reduction -> final scalar.
// ---------------------------------------------------------------------------
__global__ void k_final(const int* __restrict__ labels,
                        const unsigned char* __restrict__ mask,
                        float* __restrict__ out) {
    __shared__ float contrib[CC];
    __shared__ int   cnt[CC];
    int t = threadIdx.x;
    if (t < CC) { contrib[t] = 0.0f; cnt[t] = 0; }
    __syncthreads();
    for (int n = t; n < NN; n += blockDim.x) {
        if (mask[n]) {
            int c = labels[n];
            atomicAdd(&contrib[c], g_pixterm[n]);
            atomicAdd(&cnt[c], 1);
        }
    }
    __syncthreads();
    if (t == 0) {
        float loss = 0.0f, ccount = 0.0f;
        for (int i = 0; i < CC; i++) {
            if (cnt[i] > 0) {
                loss += contrib[i] / ((float)cnt[i] * (float)SS);
                ccount += 1.0f;
            }
        }
        out[0] = loss / fmaxf(ccount, 1.0f);
    }
}

// ---------------------------------------------------------------------------
extern "C" void kernel_launch(void* const* d_in, const int* in_sizes, int n_in,
                              void* d_out, int out_size) {
    const float*         mem    = (const float*)d_in[0];         // (19,512,256)
    const float*         pred   = (const float*)d_in[1];         // (4,256,64,64)
    const int*           labels = (const int*)d_in[2];           // (4,64,64)
    const unsigned char* mask   = (const unsigned char*)d_in[3]; // bool (1B)
    const int*           wm     = (const int*)d_in[4];           // (4,64,64)
    float*               out    = (float*)d_out;

    (void)in_sizes; (void)n_in; (void)out_size;

    k_prep_feats<<<dim3(BB, HH / 4), 256>>>(pred);
    k_prep_mem<<<MM, 128>>>(mem);
    k_gemm<<<dim3(MM / 128, NN / 128), 256>>>(labels);
    k_terms<<<NN / 8, 256>>>(mask, wm);
    k_final<<<1, 256>>>(labels, mask, out);
}

// round 6
// speedup vs baseline: 5.7407x; 1.2795x over previous
#include <cuda_runtime.h>
#include <cuda_bf16.h>
#include <math.h>
#include <stdint.h>

// Problem constants (fixed shapes)
#define BB 4
#define HH 64
#define WW 64
#define FF 256
#define CC 19
#define SS 256
#define TWOS (2*SS)            // 512
#define NN (BB*HH*WW)          // 16384 pixels
#define MM (CC*TWOS)           // 9728 memory vectors

// Scratch (static device globals; no allocation at runtime)
__device__ __nv_bfloat16 g_A[NN * FF];   // normalized feats, [n][f] row-major (8 MB)
__device__ __nv_bfloat16 g_Bm[MM * FF];  // normalized memory, [m][f] row-major (5 MB)
__device__ float g_total[NN];            // per-pixel sum of exp(cos/temp)
__device__ float g_blocksum[NN];         // per-pixel own-block sum of exp
__device__ float g_owncos[NN * TWOS];    // per-pixel own-class-block cos (33.5 MB)
__device__ float g_pixterm[NN];          // per-pixel positive-term sum

// ---------------------------------------------------------------------------
// exp(2*c) on the FMA pipe: 2^(c*2*log2e), range-reduce + deg-5 Taylor +
// exponent splice. c in [-1.01, 1.01]; rel err ~2.4e-6.
// ---------------------------------------------------------------------------
__device__ __forceinline__ float fexp2c(float c) {
    float y = c * 2.8853900817779268f;   // 2 * log2(e)
    float n = rintf(y);
    float t = (y - n) * 0.6931471805599453f;
    float p = 1.0f + t * (1.0f + t * (0.5f + t * (0.16666667f
                  + t * (0.041666668f + t * 0.008333334f))));
    return __int_as_float(__float_as_int(p) + (((int)n) << 23));
}

__device__ __forceinline__ void cp16(uint32_t smem_dst, const void* gsrc) {
    asm volatile("cp.async.cg.shared.global [%0], [%1], 16;\n" :: "r"(smem_dst), "l"(gsrc));
}

__device__ __forceinline__ uint32_t smem_u32(const void* p) {
    uint32_t a;
    asm("{ .reg .u64 t; cvta.to.shared.u64 t, %1; cvt.u32.u64 %0, t; }" : "=r"(a) : "l"(p));
    return a;
}

__device__ __forceinline__ void ldm_x4(uint32_t* r, uint32_t addr) {
    asm volatile("ldmatrix.sync.aligned.m8n8.x4.shared.b16 {%0,%1,%2,%3}, [%4];"
        : "=r"(r[0]), "=r"(r[1]), "=r"(r[2]), "=r"(r[3]) : "r"(addr));
}

__device__ __forceinline__ void mma16816(float* d, const uint32_t* a, const uint32_t* b) {
    asm volatile(
        "mma.sync.aligned.m16n8k16.row.col.f32.bf16.bf16.f32 "
        "{%0,%1,%2,%3}, {%4,%5,%6,%7}, {%8,%9}, {%0,%1,%2,%3};\n"
        : "+f"(d[0]), "+f"(d[1]), "+f"(d[2]), "+f"(d[3])
        : "r"(a[0]), "r"(a[1]), "r"(a[2]), "r"(a[3]), "r"(b[0]), "r"(b[1]));
}

// ---------------------------------------------------------------------------
// K1a: normalize feats. pred_rep is (B,F,H,W). Write bf16 [n][f] row-major.
// Also zero g_total/g_blocksum (rewritten each launch -> graph-deterministic).
// ---------------------------------------------------------------------------
__global__ void k_prep_feats(const float* __restrict__ pred) {
    int t = threadIdx.x;
    int w = t & 63;
    int h = blockIdx.y * 4 + (t >> 6);
    int b = blockIdx.x;
    int n = (b * HH + h) * WW + w;
    const float* base = pred + (size_t)b * FF * HH * WW + h * WW + w;

    float sumsq = 0.0f;
    #pragma unroll 8
    for (int f = 0; f < FF; f++) {
        float v = base[f * (HH * WW)];
        sumsq += v * v;
    }
    float inv = rsqrtf(sumsq);

    for (int f0 = 0; f0 < FF; f0 += 8) {
        __nv_bfloat16 h8[8];
        #pragma unroll
        for (int j = 0; j < 8; j++)
            h8[j] = __float2bfloat16(base[(f0 + j) * (HH * WW)] * inv);
        *(uint4*)&g_A[n * FF + f0] = *(const uint4*)h8;
    }
    g_total[n] = 0.0f;
    g_blocksum[n] = 0.0f;
}

// ---------------------------------------------------------------------------
// K1b: normalize memory rows -> bf16 [m][f]. One block (128 thr) per row.
// ---------------------------------------------------------------------------
__global__ void k_prep_mem(const float* __restrict__ mem) {
    __shared__ float red[4];
    int m = blockIdx.x;
    int t = threadIdx.x;
    float2 v = *(const float2*)&mem[m * FF + 2 * t];
    float p = v.x * v.x + v.y * v.y;
    #pragma unroll
    for (int o = 16; o > 0; o >>= 1) p += __shfl_down_sync(0xffffffffu, p, o);
    if ((t & 31) == 0) red[t >> 5] = p;
    __syncthreads();
    float inv = rsqrtf(red[0] + red[1] + red[2] + red[3]);
    __nv_bfloat162 o2;
    o2.x = __float2bfloat16(v.x * inv);
    o2.y = __float2bfloat16(v.y * inv);
    *(__nv_bfloat162*)&g_Bm[m * FF + 2 * t] = o2;
}

// ---------------------------------------------------------------------------
// K2: bf16 HMMA GEMM (128 pix x 128 mem x K=256), ldmatrix fragment loads,
// XOR-swizzled smem, BK=64 double-buffered cp.async. 8 warps, warp tile
// 32 (pix) x 64 (mem). Epilogue: poly-exp row sums + own-block sum +
// own-class cos scatter.
// ---------------------------------------------------------------------------
// Dynamic smem layout (bytes): labels[128] @0, rowsum @512, blksum @1024,
// A bufs @2048 (2 x 16KB), B bufs @34816 (2 x 16KB). Total 67584.
#define SM_LAB   0
#define SM_PART  512
#define SM_BPART 1024
#define SM_A     2048
#define SM_B     (2048 + 32768)
#define SM_TOTAL (2048 + 65536)

__global__ __launch_bounds__(256, 2) void k_gemm(const int* __restrict__ labels) {
    extern __shared__ __align__(1024) char dsm[];
    uint32_t sb = smem_u32(dsm);

    int tid = threadIdx.x;
    int m0 = blockIdx.x * 128;
    int n0 = blockIdx.y * 128;
    int wid = tid >> 5, lane = tid & 31;
    int wm = wid & 3;          // pixel-dir warp (4)
    int wn = wid >> 2;         // mem-dir warp (2)
    int g = lane >> 2, t4 = lane & 3;
    int l15 = lane & 15, l16 = lane >> 4;

    float* s_rowsum = (float*)(dsm + SM_PART);
    float* s_blksum = (float*)(dsm + SM_BPART);
    int*   s_lab    = (int*)(dsm + SM_LAB);

    if (tid < 128) {
        s_rowsum[tid] = 0.0f;
        s_blksum[tid] = 0.0f;
        s_lab[tid] = labels[n0 + tid];
    }

    float acc[2][8][4];
    #pragma unroll
    for (int mi = 0; mi < 2; mi++)
        #pragma unroll
        for (int ni = 0; ni < 8; ni++)
            #pragma unroll
            for (int q = 0; q < 4; q++) acc[mi][ni][q] = 0.0f;

    // Fill one BK=64 double-buffer slice: 1024 16B chunks each for A and B.
#define ISSUE(IT, BUF) do {                                                     \
        int k0_ = (IT) * 64;                                                    \
        _Pragma("unroll")                                                       \
        for (int r_ = 0; r_ < 4; r_++) {                                        \
            int id = tid + r_ * 256;          /* 0..1023 */                     \
            int row = id >> 3, c = id & 7;                                      \
            int sw = (c ^ (row & 7)) << 4;                                      \
            cp16(sb + SM_A + (BUF) * 16384 + row * 128 + sw,                    \
                 &g_A[(size_t)(n0 + row) * FF + k0_ + c * 8]);                  \
            cp16(sb + SM_B + (BUF) * 16384 + row * 128 + sw,                    \
                 &g_Bm[(size_t)(m0 + row) * FF + k0_ + c * 8]);                 \
        } } while (0)

    ISSUE(0, 0);
    asm volatile("cp.async.commit_group;\n");

    #pragma unroll
    for (int it = 0; it < 4; it++) {
        int buf = it & 1;
        if (it < 3) ISSUE(it + 1, buf ^ 1);
        asm volatile("cp.async.commit_group;\n");
        asm volatile("cp.async.wait_group 1;\n");
        __syncthreads();

        uint32_t Ab = sb + SM_A + buf * 16384;
        uint32_t Bb = sb + SM_B + buf * 16384;
        #pragma unroll
        for (int ks = 0; ks < 4; ks++) {
            int kc = ks * 2 + l16;
            uint32_t a[2][4], b[4][4];
            #pragma unroll
            for (int mi = 0; mi < 2; mi++) {
                int row = wm * 32 + mi * 16 + l15;
                ldm_x4(a[mi], Ab + row * 128 + ((kc ^ (row & 7)) << 4));
            }
            #pragma unroll
            for (int nj = 0; nj < 4; nj++) {
                int row = wn * 64 + nj * 16 + l15;
                ldm_x4(b[nj], Bb + row * 128 + ((kc ^ (row & 7)) << 4));
            }
            #pragma unroll
            for (int mi = 0; mi < 2; mi++)
                #pragma unroll
                for (int nj = 0; nj < 4; nj++) {
                    uint32_t b0[2] = { b[nj][0], b[nj][2] };
                    uint32_t b1[2] = { b[nj][1], b[nj][3] };
                    mma16816(acc[mi][2 * nj],     a[mi], b0);
                    mma16816(acc[mi][2 * nj + 1], a[mi], b1);
                }
        }
        __syncthreads();
    }
#undef ISSUE

    // Epilogue: poly exp + row sums + own-block sums + own-class cos scatter
    int cls = m0 >> 9;                       // tile never straddles class blocks
    int mrel = (m0 & 511) + wn * 64;         // offset within 512-wide class block

    #pragma unroll
    for (int mi = 0; mi < 2; mi++) {
        int rbase = wm * 32 + mi * 16;
        int p0 = rbase + g;
        int p1 = rbase + 8 + g;
        bool own0 = (s_lab[p0] == cls);
        bool own1 = (s_lab[p1] == cls);
        float s0 = 0.0f, s1 = 0.0f;
        #pragma unroll
        for (int ni = 0; ni < 8; ni++) {
            float d0 = acc[mi][ni][0], d1 = acc[mi][ni][1];
            float d2 = acc[mi][ni][2], d3 = acc[mi][ni][3];
            s0 += fexp2c(d0) + fexp2c(d1);
            s1 += fexp2c(d2) + fexp2c(d3);
            int mo = mrel + ni * 8 + t4 * 2;
            if (own0) {
                g_owncos[(size_t)(n0 + p0) * TWOS + mo]     = d0;
                g_owncos[(size_t)(n0 + p0) * TWOS + mo + 1] = d1;
            }
            if (own1) {
                g_owncos[(size_t)(n0 + p1) * TWOS + mo]     = d2;
                g_owncos[(size_t)(n0 + p1) * TWOS + mo + 1] = d3;
            }
        }
        s0 += __shfl_xor_sync(0xffffffffu, s0, 1);
        s0 += __shfl_xor_sync(0xffffffffu, s0, 2);
        s1 += __shfl_xor_sync(0xffffffffu, s1, 1);
        s1 += __shfl_xor_sync(0xffffffffu, s1, 2);
        if (t4 == 0) {
            atomicAdd(&s_rowsum[p0], s0);
            atomicAdd(&s_rowsum[p1], s1);
            if (own0) atomicAdd(&s_blksum[p0], s0);
            if (own1) atomicAdd(&s_blksum[p1], s1);
        }
    }
    __syncthreads();
    if (tid < 128) {
        atomicAdd(&g_total[n0 + tid], s_rowsum[tid]);
        float bsv = s_blksum[tid];
        if (bsv != 0.0f) atomicAdd(&g_blocksum[n0 + tid], bsv);
    }
}

// ---------------------------------------------------------------------------
// K3: one warp per pixel. down = total - blocksum; only the wm-selected
// half (256 values): sum -log(pos/(pos+down+eps)+eps).
// ---------------------------------------------------------------------------
__global__ void k_terms(const unsigned char* __restrict__ mask,
                        const int* __restrict__ wm) {
    int gw   = (blockIdx.x * blockDim.x + threadIdx.x) >> 5;
    int lane = threadIdx.x & 31;
    if (gw >= NN) return;
    int n = gw;

    int wv = wm[n];
    int hb = (wv == 1) ? 0 : SS;   // wm==1 -> net0 -> first half
    float down = g_total[n] - g_blocksum[n];

    float ts = 0.0f;
    #pragma unroll
    for (int k = 0; k < 8; k++) {
        float c = g_owncos[(size_t)n * TWOS + hb + lane + 32 * k];
        float pos = fexp2c(c);
        float r = pos / (pos + down + 1e-12f);
        ts += -logf(r + 1e-12f);
    }
    #pragma unroll
    for (int o = 16; o > 0; o >>= 1) ts += __shfl_xor_sync(0xffffffffu, ts, o);

    if (lane == 0) g_pixterm[n] = mask[n] ? ts : 0.0f;
}

// ---------------------------------------------------------------------------
// K4: per-class reduction -> final scalar.
// ---------------------------------------------------------------------------
__global__ void k_final(const int* __restrict__ labels,
                        const unsigned char* __restrict__ mask,
                        float* __restrict__ out) {
    __shared__ float contrib[CC];
    __shared__ int   cnt[CC];
    int t = threadIdx.x;
    if (t < CC) { contrib[t] = 0.0f; cnt[t] = 0; }
    __syncthreads();
    for (int n = t; n < NN; n += blockDim.x) {
        if (mask[n]) {
            int c = labels[n];
            atomicAdd(&contrib[c], g_pixterm[n]);
            atomicAdd(&cnt[c], 1);
        }
    }
    __syncthreads();
    if (t == 0) {
        float loss = 0.0f, ccount = 0.0f;
        for (int i = 0; i < CC; i++) {
            if (cnt[i] > 0) {
                loss += contrib[i] / ((float)cnt[i] * (float)SS);
                ccount += 1.0f;
            }
        }
        out[0] = loss / fmaxf(ccount, 1.0f);
    }
}

// ---------------------------------------------------------------------------
extern "C" void kernel_launch(void* const* d_in, const int* in_sizes, int n_in,
                              void* d_out, int out_size) {
    const float*         mem    = (const float*)d_in[0];         // (19,512,256)
    const float*         pred   = (const float*)d_in[1];         // (4,256,64,64)
    const int*           labels = (const int*)d_in[2];           // (4,64,64)
    const unsigned char* mask   = (const unsigned char*)d_in[3]; // bool (1B)
    const int*           wm     = (const int*)d_in[4];           // (4,64,64)
    float*               out    = (float*)d_out;

    (void)in_sizes; (void)n_in; (void)out_size;

    cudaFuncSetAttribute(k_gemm, cudaFuncAttributeMaxDynamicSharedMemorySize, SM_TOTAL);

    k_prep_feats<<<dim3(BB, HH / 4), 256>>>(pred);
    k_prep_mem<<<MM, 128>>>(mem);
    k_gemm<<<dim3(MM / 128, NN / 128), 256, SM_TOTAL>>>(labels);
    k_terms<<<NN / 8, 256>>>(mask, wm);
    k_final<<<1, 256>>>(labels, mask, out);
}